// round 12
// baseline (speedup 1.0000x reference)
#include <cuda_runtime.h>
#include <cstddef>

#define IMG_H 128
#define IMG_W 128

// ---------------------------------------------------------------------------
// Single fused kernel (R10 winner, block granularity halved to (32,4) for
// smoother wave scheduling). Each warp handles TWO image rows (y0, y0+1) of
// one batch image and independently recomputes the 8 GLT integer cutoffs
// (no smem, no __syncthreads, overlapped with loads).
//
// Cutoffs: ct[t] = min{k in 0..255 : x(k) >= thr[t]}, else 256, where
// x(k) = fl(fl(k*C) - 1), C = fl(1/127.5) — exact XLA rounding. Analytic
// inversion g = (thr+1)*127.5 locates the cutoff to within +-0.01; the
// 8-candidate window [g-3, g+4] with exact x(k) evaluation gives exact min k.
//
// Stores use __stcs (evict_first): the 134 MB write-once output drains to
// DRAM during the kernel window instead of trailing the kernel (R10-verified:
// total 28.8 -> 25.1 us with kernel duration unchanged).
// Block (32,4) = 8 rows; grid (16, 256).
// ---------------------------------------------------------------------------
__global__ __launch_bounds__(128) void lbp_glt_fused_kernel(
    const float* __restrict__ img, const float* __restrict__ lt,
    float* __restrict__ out) {
    const unsigned FULL = 0xffffffffu;
    const int lane = threadIdx.x;
    const int y0   = (blockIdx.x * 4 + threadIdx.y) * 2;   // rows y0, y0+1
    const int b    = blockIdx.y;

    // ---- issue lt loads first (broadcast across lanes; feeds cutoff math) --
    const float4 ltA = *reinterpret_cast<const float4*>(lt);
    const float4 ltB = *reinterpret_cast<const float4*>(lt + 4);

    // ---- front-batched image loads: rows y0-1 .. y0+2 (zero pad OOB) ----
    const float* row = img + ((size_t)b * IMG_H + y0) * IMG_W + lane * 4;
    const float4 Z = make_float4(0.f, 0.f, 0.f, 0.f);
    float4 r0 = Z, r1, r2, r3 = Z;
    if (y0 > 0)              r0 = *reinterpret_cast<const float4*>(row - IMG_W);
    r1 = *reinterpret_cast<const float4*>(row);
    r2 = *reinterpret_cast<const float4*>(row + IMG_W);      // y0+1 <= 127
    if (y0 + 2 < IMG_H)      r3 = *reinterpret_cast<const float4*>(row + 2 * IMG_W);

    // ---- cutoff math (lane-redundant; overlaps image load latency) ----
    float p[8];
    p[0] = __fadd_rn(fmaxf(ltA.x, 0.0f), 1e-5f);
    p[1] = __fadd_rn(fmaxf(ltA.y, 0.0f), 1e-5f);
    p[2] = __fadd_rn(fmaxf(ltA.z, 0.0f), 1e-5f);
    p[3] = __fadd_rn(fmaxf(ltA.w, 0.0f), 1e-5f);
    p[4] = __fadd_rn(fmaxf(ltB.x, 0.0f), 1e-5f);
    p[5] = __fadd_rn(fmaxf(ltB.y, 0.0f), 1e-5f);
    p[6] = __fadd_rn(fmaxf(ltB.z, 0.0f), 1e-5f);
    p[7] = __fadd_rn(fmaxf(ltB.w, 0.0f), 1e-5f);

    float S = p[0];                                       // sequential sum
#pragma unroll
    for (int i = 1; i < 8; i++) S = __fadd_rn(S, p[i]);

    float n[8];
#pragma unroll
    for (int i = 0; i < 8; i++) n[i] = __fdiv_rn(p[i], S);

    // cumsum via associative_scan tree order (n=8)
    const float b0 = __fadd_rn(n[0], n[1]);
    const float b1 = __fadd_rn(n[2], n[3]);
    const float b2 = __fadd_rn(n[4], n[5]);
    const float b3 = __fadd_rn(n[6], n[7]);
    const float c0 = __fadd_rn(b0, b1);
    const float c1 = __fadd_rn(b2, b3);
    float r[8];
    r[0] = n[0];
    r[1] = b0;
    r[2] = __fadd_rn(b0, n[2]);
    r[3] = c0;
    r[4] = __fadd_rn(c0, n[4]);
    r[5] = __fadd_rn(c0, b2);
    r[6] = __fadd_rn(__fadd_rn(c0, b2), n[6]);
    r[7] = __fadd_rn(c0, c1);

    // this lane resolves threshold t = lane & 7
    const int   t   = lane & 7;
    const float thr = __fsub_rn(__fmul_rn(r[t], 2.0f), 1.0f);
    const float C   = (float)(1.0 / 127.5);
    const float gf  = __fmul_rn(__fadd_rn(thr, 1.0f), 127.5f);
    int lo = (int)floorf(gf) - 3;
    if (lo < 0) lo = 0;
    int ctv = 256;                                        // "never" sentinel
#pragma unroll
    for (int j = 0; j < 8; j++) {
        const int   k  = lo + j;
        const float xk = __fsub_rn(__fmul_rn((float)k, C), 1.0f); // exact x(k)
        if (k <= 255 && xk >= thr && k < ctv) ctv = k;
    }
    // gather this lane's int4 of cutoffs (even lanes ct[0..3], odd ct[4..7])
    const int base = (lane & 1) * 4;
    int4 ct;
    ct.x = __shfl_sync(FULL, ctv, base + 0);
    ct.y = __shfl_sync(FULL, ctv, base + 1);
    ct.z = __shfl_sync(FULL, ctv, base + 2);
    ct.w = __shfl_sync(FULL, ctv, base + 3);

    // ---- column halos via shuffle (image border -> 0) ----
    float L0 = __shfl_up_sync(FULL, r0.w, 1);
    float L1 = __shfl_up_sync(FULL, r1.w, 1);
    float L2 = __shfl_up_sync(FULL, r2.w, 1);
    float L3 = __shfl_up_sync(FULL, r3.w, 1);
    float R0 = __shfl_down_sync(FULL, r0.x, 1);
    float R1 = __shfl_down_sync(FULL, r1.x, 1);
    float R2 = __shfl_down_sync(FULL, r2.x, 1);
    float R3 = __shfl_down_sync(FULL, r3.x, 1);
    if (lane == 0)  { L0 = 0.f; L1 = 0.f; L2 = 0.f; L3 = 0.f; }
    if (lane == 31) { R0 = 0.f; R1 = 0.f; R2 = 0.f; R3 = 0.f; }

    const float W0[6] = {L0, r0.x, r0.y, r0.z, r0.w, R0};
    const float W1[6] = {L1, r1.x, r1.y, r1.z, r1.w, R1};
    const float W2[6] = {L2, r2.x, r2.y, r2.z, r2.w, R2};
    const float W3[6] = {L3, r3.x, r3.y, r3.z, r3.w, R3};

    // ---- census codes, 4 px per row packed 8-bit; _NEIGHBORS order ----
    auto census4 = [&](const float* T, const float* M, const float* B) {
        unsigned pk = 0;
#pragma unroll
        for (int j = 0; j < 4; j++) {
            const float c = M[j + 1];
            unsigned code = (T[j]     >= c ? 1u   : 0u)
                          | (T[j + 1] >= c ? 2u   : 0u)
                          | (T[j + 2] >= c ? 4u   : 0u)
                          | (M[j + 2] >= c ? 8u   : 0u)
                          | (B[j + 2] >= c ? 16u  : 0u)
                          | (B[j + 1] >= c ? 32u  : 0u)
                          | (B[j]     >= c ? 64u  : 0u)
                          | (M[j]     >= c ? 128u : 0u);
            pk |= code << (j * 8);
        }
        return pk;
    };
    const unsigned packA = census4(W0, W1, W2);   // row y0
    const unsigned packB = census4(W1, W2, W3);   // row y0+1

    // ---- stores: 8 lane-contiguous STG.128 (evict-first) rounds per row ----
    float4* orow = reinterpret_cast<float4*>(
        out + ((size_t)b * IMG_H + y0) * (IMG_W * 8));
    const int src_lane = (lane >> 3);             // + j*4 per round
    const int byte_sh  = ((lane >> 1) & 3) * 8;

    auto store_row = [&](unsigned pack, float4* dst) {
#pragma unroll
        for (int j = 0; j < 8; j++) {
            const unsigned pk = __shfl_sync(FULL, pack, j * 4 + src_lane);
            const int code = (int)((pk >> byte_sh) & 0xffu);
            float4 o;
            o.x = (code >= ct.x) ? 1.0f : 0.0f;
            o.y = (code >= ct.y) ? 1.0f : 0.0f;
            o.z = (code >= ct.z) ? 1.0f : 0.0f;
            o.w = (code >= ct.w) ? 1.0f : 0.0f;
            __stcs(&dst[j * 32 + lane], o);       // streaming: evict-first
        }
    };
    store_row(packA, orow);
    store_row(packB, orow + IMG_W * 8 / 4);       // next row: 256 float4s
}

extern "C" void kernel_launch(void* const* d_in, const int* in_sizes, int n_in,
                              void* d_out, int out_size) {
    const float* images = (const float*)d_in[0];
    const float* latent = (const float*)d_in[1];
    float* out = (float*)d_out;

    const int B = in_sizes[0] / (IMG_H * IMG_W);

    dim3 block(32, 4, 1);
    dim3 grid(IMG_H / 8, B, 1);   // 16 x 256 = 4096 blocks, 8 rows per block
    lbp_glt_fused_kernel<<<grid, block>>>(images, latent, out);
}